// round 2
// baseline (speedup 1.0000x reference)
#include <cuda_runtime.h>

#define NMAX  100000
#define NF    512
#define NH    8
#define NC    16

// ---------------- scratch (no allocations allowed) ----------------
__device__ float g_s1[NMAX * NH];    // x @ W1 (pre-spmm)
__device__ float g_xr[NMAX * NH];    // affine(relu(bi-interaction))
__device__ float g_agg1[NMAX * NH];  // spmm(adj, s1)
__device__ float g_s2[NMAX * NC];    // h @ W2

typedef unsigned long long u64;

// ---------------- f32x2 helpers (FFMA2 = full-rate fp32 on sm_103a) ---
#define PACK2(out, lo, hi) \
    asm("mov.b64 %0, {%1, %2};" : "=l"(out) : "f"(lo), "f"(hi))
#define UNPACK2(lo, hi, in) \
    asm("mov.b64 {%0, %1}, %2;" : "=f"(lo), "=f"(hi) : "l"(in))
#define MUL2(out, a, b) \
    asm("mul.rn.f32x2 %0, %1, %2;" : "=l"(out) : "l"(a), "l"(b))
#define FMA2(acc, a, b) \
    asm("fma.rn.f32x2 %0, %1, %2, %0;" : "+l"(acc) : "l"(a), "l"(b))

__device__ __forceinline__ void redv4(float* p, float a, float b, float c, float d) {
    asm volatile("red.global.add.v4.f32 [%0], {%1,%2,%3,%4};"
                 :: "l"(p), "f"(a), "f"(b), "f"(c), "f"(d) : "memory");
}

// ---------------- kernel 0: zero the atomic accumulators --------------
__global__ void k_zero(float* __restrict__ out, int n) {
    int i = blockIdx.x * blockDim.x + threadIdx.x;
    int n1 = n * NH / 4;   // float4 count in g_agg1
    int n2 = n * NC / 4;   // float4 count in out
    float4 z = make_float4(0.f, 0.f, 0.f, 0.f);
    if (i < n1) ((float4*)g_agg1)[i] = z;
    if (i < n2) ((float4*)out)[i] = z;
}

// ---------------- kernel 1: fused x@W1 / x@V / x^2@V^2 ----------------
// One thread = one node, all 24 outputs. Weights live in SMEM and every
// lane in a warp reads the SAME weight address -> broadcast (conflict-free).
// k-pairs packed into f32x2 accumulators.
#define KCHUNK 64
#define XPITCH 68   // 64 + 4 pad: keeps float4 align (272B) and spreads banks

__global__ void __launch_bounds__(256) k_gemmA(
    const float* __restrict__ x, const float* __restrict__ W1,
    const float* __restrict__ V, const float* __restrict__ gamma,
    const float* __restrict__ beta, int n)
{
    extern __shared__ float sm[];
    float* wT = sm;                 // [24][512]  (48 KB)
    float* xs = sm + 24 * NF;       // [256][68]  (68 KB)
    const int tid = threadIdx.x;
    const int nb  = blockIdx.x * 256;

    // stage combined weights, transposed to [out][k]
    for (int i = tid; i < NF * NH; i += 256) {
        int k = i >> 3, h = i & 7;
        float a = W1[i];
        float b = V[i];
        wT[h * NF + k]        = a;
        wT[(8 + h) * NF + k]  = b;
        wT[(16 + h) * NF + k] = b * b;
    }

    u64 a1[8], av[8], a2[8];
#pragma unroll
    for (int h = 0; h < 8; h++) { a1[h] = 0ull; av[h] = 0ull; a2[h] = 0ull; }

    for (int kc = 0; kc < NF; kc += KCHUNK) {
        __syncthreads();
        // stage x chunk [256 nodes][64 k] coalesced
        for (int idx = tid; idx < 256 * 16; idx += 256) {
            int r = idx >> 4, c4 = idx & 15;
            int gn = nb + r;
            float4 val = make_float4(0.f, 0.f, 0.f, 0.f);
            if (gn < n) val = *(const float4*)(x + (size_t)gn * NF + kc + c4 * 4);
            *(float4*)(xs + r * XPITCH + c4 * 4) = val;
        }
        __syncthreads();

#pragma unroll 2
        for (int kk = 0; kk < KCHUNK; kk += 4) {
            float4 xf = *(const float4*)(xs + tid * XPITCH + kk);
            u64 xA, xB, xA2, xB2;
            PACK2(xA, xf.x, xf.y);
            PACK2(xB, xf.z, xf.w);
            MUL2(xA2, xA, xA);
            MUL2(xB2, xB, xB);
            const float* wb = wT + kc + kk;
#pragma unroll
            for (int h = 0; h < 8; h++) {
                float4 w1f = *(const float4*)(wb + h * NF);          // broadcast
                float4 vf  = *(const float4*)(wb + (8 + h) * NF);    // broadcast
                float4 v2f = *(const float4*)(wb + (16 + h) * NF);   // broadcast
                u64 t;
                PACK2(t, w1f.x, w1f.y); FMA2(a1[h], xA,  t);
                PACK2(t, w1f.z, w1f.w); FMA2(a1[h], xB,  t);
                PACK2(t, vf.x,  vf.y);  FMA2(av[h], xA,  t);
                PACK2(t, vf.z,  vf.w);  FMA2(av[h], xB,  t);
                PACK2(t, v2f.x, v2f.y); FMA2(a2[h], xA2, t);
                PACK2(t, v2f.z, v2f.w); FMA2(a2[h], xB2, t);
            }
        }
    }

    int node = nb + tid;
    if (node < n) {
#pragma unroll
        for (int h = 0; h < 8; h++) {
            float l0, l1;
            UNPACK2(l0, l1, a1[h]); float s1v  = l0 + l1;
            UNPACK2(l0, l1, av[h]); float xv   = l0 + l1;
            UNPACK2(l0, l1, a2[h]); float x2v2 = l0 + l1;
            float r = 0.5f * (xv * xv - x2v2);
            r = r > 0.f ? r : 0.f;
            g_s1[(size_t)node * NH + h] = s1v;
            g_xr[(size_t)node * NH + h] = gamma[h] * r + beta[h];
        }
    }
}

// ---------------- kernel 2: spmm1 (COO, vector atomics) ---------------
__global__ void k_spmm1(const int* __restrict__ rows, const int* __restrict__ cols,
                        const float* __restrict__ vals, int e)
{
    int i = blockIdx.x * blockDim.x + threadIdx.x;
    if (i >= e) return;
    int   r = rows[i];
    int   c = cols[i];
    float v = vals[i];
    const float4* s = (const float4*)(g_s1 + (size_t)c * NH);
    float4 p0 = s[0], p1 = s[1];
    float* dst = g_agg1 + (size_t)r * NH;
    redv4(dst,     v * p0.x, v * p0.y, v * p0.z, v * p0.w);
    redv4(dst + 4, v * p1.x, v * p1.y, v * p1.z, v * p1.w);
}

// ---------------- kernel 3: relu+bias, merge branches, h@W2 -----------
__global__ void k_mid(const float* __restrict__ b1, const float* __restrict__ W2, int n)
{
    __shared__ float w2s[NH * NC];
    __shared__ float b1s[NH];
    int tid = threadIdx.x;
    if (tid < NH * NC) w2s[tid] = W2[tid];
    if (tid < NH)      b1s[tid] = b1[tid];
    __syncthreads();
    int node = blockIdx.x * blockDim.x + tid;
    if (node >= n) return;
    float h[NH];
#pragma unroll
    for (int j = 0; j < NH; j++) {
        float l = g_agg1[(size_t)node * NH + j] + b1s[j];
        l = l > 0.f ? l : 0.f;
        h[j] = 0.5f * (l + g_xr[(size_t)node * NH + j]);
    }
#pragma unroll
    for (int c = 0; c < NC; c++) {
        float acc = 0.f;
#pragma unroll
        for (int j = 0; j < NH; j++) acc = fmaf(h[j], w2s[j * NC + c], acc);
        g_s2[(size_t)node * NC + c] = acc;
    }
}

// ---------------- kernel 4: spmm2 into d_out --------------------------
__global__ void k_spmm2(const int* __restrict__ rows, const int* __restrict__ cols,
                        const float* __restrict__ vals, float* __restrict__ out, int e)
{
    int i = blockIdx.x * blockDim.x + threadIdx.x;
    if (i >= e) return;
    int   r = rows[i];
    int   c = cols[i];
    float v = vals[i];
    const float4* s = (const float4*)(g_s2 + (size_t)c * NC);
    float* dst = out + (size_t)r * NC;
#pragma unroll
    for (int q = 0; q < 4; q++) {
        float4 p = s[q];
        redv4(dst + q * 4, v * p.x, v * p.y, v * p.z, v * p.w);
    }
}

// ---------------- kernel 5: + b2, log_softmax (in place) --------------
__global__ void k_lsm(float* __restrict__ out, const float* __restrict__ b2, int n)
{
    __shared__ float b2s[NC];
    if (threadIdx.x < NC) b2s[threadIdx.x] = b2[threadIdx.x];
    __syncthreads();
    int node = blockIdx.x * blockDim.x + threadIdx.x;
    if (node >= n) return;
    float v[NC];
    float4* p = (float4*)(out + (size_t)node * NC);
#pragma unroll
    for (int q = 0; q < 4; q++) {
        float4 t = p[q];
        v[q * 4 + 0] = t.x + b2s[q * 4 + 0];
        v[q * 4 + 1] = t.y + b2s[q * 4 + 1];
        v[q * 4 + 2] = t.z + b2s[q * 4 + 2];
        v[q * 4 + 3] = t.w + b2s[q * 4 + 3];
    }
    float m = v[0];
#pragma unroll
    for (int c = 1; c < NC; c++) m = fmaxf(m, v[c]);
    float s = 0.f;
#pragma unroll
    for (int c = 0; c < NC; c++) s += expf(v[c] - m);
    float lse = m + logf(s);
#pragma unroll
    for (int q = 0; q < 4; q++) {
        float4 t;
        t.x = v[q * 4 + 0] - lse;
        t.y = v[q * 4 + 1] - lse;
        t.z = v[q * 4 + 2] - lse;
        t.w = v[q * 4 + 3] - lse;
        p[q] = t;
    }
}

// ---------------- launcher -------------------------------------------
extern "C" void kernel_launch(void* const* d_in, const int* in_sizes, int n_in,
                              void* d_out, int out_size)
{
    const float* x     = (const float*)d_in[0];
    const int*   rows  = (const int*)d_in[1];
    const int*   cols  = (const int*)d_in[2];
    const float* vals  = (const float*)d_in[3];
    const float* W1    = (const float*)d_in[4];
    const float* b1    = (const float*)d_in[5];
    const float* W2    = (const float*)d_in[6];
    const float* b2    = (const float*)d_in[7];
    const float* V     = (const float*)d_in[8];
    const float* gamma = (const float*)d_in[9];
    const float* beta  = (const float*)d_in[10];
    float* out = (float*)d_out;

    int n = in_sizes[0] / NF;   // 100000
    int e = in_sizes[1];        // 3200000

    int smem = (24 * NF + 256 * XPITCH) * (int)sizeof(float);
    cudaFuncSetAttribute(k_gemmA, cudaFuncAttributeMaxDynamicSharedMemorySize, smem);

    {   // zero g_agg1 + d_out
        int n2 = n * NC / 4;
        int blocks = (n2 + 255) / 256;
        k_zero<<<blocks, 256>>>(out, n);
    }
    {   // fused input GEMM
        int blocks = (n + 255) / 256;
        k_gemmA<<<blocks, 256, smem>>>(x, W1, V, gamma, beta, n);
    }
    {   // spmm1
        int blocks = (e + 255) / 256;
        k_spmm1<<<blocks, 256>>>(rows, cols, vals, e);
    }
    {   // mid
        int blocks = (n + 255) / 256;
        k_mid<<<blocks, 256>>>(b1, W2, n);
    }
    {   // spmm2
        int blocks = (e + 255) / 256;
        k_spmm2<<<blocks, 256>>>(rows, cols, vals, out, e);
    }
    {   // log_softmax
        int blocks = (n + 255) / 256;
        k_lsm<<<blocks, 256>>>(out, b2, n);
    }
}

// round 3
// speedup vs baseline: 1.3921x; 1.3921x over previous
#include <cuda_runtime.h>

#define NMAX  100000
#define EMAX  3200000
#define NF    512
#define NH    8
#define NC    16

// ---------------- scratch (no allocations allowed) ----------------
__device__ float g_s1[NMAX * NH];          // x @ W1 (pre-spmm)
__device__ float g_xr[NMAX * NH];          // affine(relu(bi-interaction))
__device__ float g_s2[NMAX * NC];          // h @ W2
__device__ int   g_cnt[NMAX];              // per-row degree
__device__ int   g_offs[NMAX + 1];         // CSR row offsets
__device__ int   g_cur[NMAX];              // scatter cursors
__device__ int   g_bsum[128];              // scan block sums
__device__ int   g_boff[128];              // scan block offsets
__device__ unsigned long long g_ep[EMAX];  // packed edges: lo=col, hi=val bits

typedef unsigned long long u64;

// ---------------- f32x2 helpers (FFMA2 = full-rate fp32 on sm_103a) ---
#define UNPACK2(lo, hi, in) \
    asm("mov.b64 {%0, %1}, %2;" : "=f"(lo), "=f"(hi) : "l"(in))
#define MUL2(out, a, b) \
    asm("mul.rn.f32x2 %0, %1, %2;" : "=l"(out) : "l"(a), "l"(b))
#define FMA2(acc, a, b) \
    asm("fma.rn.f32x2 %0, %1, %2, %0;" : "+l"(acc) : "l"(a), "l"(b))

// =====================================================================
// CSR build
// =====================================================================
__global__ void k_zero_cnt(int n) {
    int i = blockIdx.x * blockDim.x + threadIdx.x;
    if (i < n) g_cnt[i] = 0;
}

__global__ void k_hist(const int* __restrict__ rows, int e) {
    int i = blockIdx.x * blockDim.x + threadIdx.x;
    if (i < e) atomicAdd(&g_cnt[rows[i]], 1);
}

#define SCAN_ELEMS 1024   // 256 threads x 4

__global__ void k_scanA(int n) {
    __shared__ int ws[8];
    int base = blockIdx.x * SCAN_ELEMS + threadIdx.x * 4;
    int s = 0;
#pragma unroll
    for (int q = 0; q < 4; q++) { int i = base + q; if (i < n) s += g_cnt[i]; }
#pragma unroll
    for (int m = 16; m; m >>= 1) s += __shfl_xor_sync(~0u, s, m);
    if ((threadIdx.x & 31) == 0) ws[threadIdx.x >> 5] = s;
    __syncthreads();
    if (threadIdx.x == 0) {
        int t = 0;
#pragma unroll
        for (int w = 0; w < 8; w++) t += ws[w];
        g_bsum[blockIdx.x] = t;
    }
}

__global__ void k_scanB(int nb) {
    __shared__ int sm_[128];
    int t = threadIdx.x;
    int v = (t < nb) ? g_bsum[t] : 0;
    sm_[t] = v;
    __syncthreads();
    for (int d = 1; d < 128; d <<= 1) {
        int add = (t >= d) ? sm_[t - d] : 0;
        __syncthreads();
        sm_[t] += add;
        __syncthreads();
    }
    if (t < nb) g_boff[t] = sm_[t] - v;  // exclusive
}

__global__ void k_scanC(int n, int e) {
    __shared__ int wtot[8];
    __shared__ int wpref[8];
    int t = threadIdx.x;
    int base = blockIdx.x * SCAN_ELEMS + t * 4;
    int v[4]; int s = 0;
#pragma unroll
    for (int q = 0; q < 4; q++) { int i = base + q; v[q] = (i < n) ? g_cnt[i] : 0; s += v[q]; }
    int lane = t & 31, wid = t >> 5;
    int sc = s;
    for (int d = 1; d < 32; d <<= 1) {
        int u = __shfl_up_sync(~0u, sc, d);
        if (lane >= d) sc += u;
    }
    if (lane == 31) wtot[wid] = sc;
    __syncthreads();
    if (t < 8) {
        int p = 0;
        for (int w = 0; w < t; w++) p += wtot[w];
        wpref[t] = p;
    }
    __syncthreads();
    int run = g_boff[blockIdx.x] + wpref[wid] + (sc - s);
#pragma unroll
    for (int q = 0; q < 4; q++) {
        int i = base + q;
        if (i < n) {
            g_offs[i] = run;
            g_cur[i]  = run;
            run += v[q];
            if (i == n - 1) g_offs[n] = e;
        }
    }
}

__global__ void k_scatter(const int* __restrict__ rows, const int* __restrict__ cols,
                          const float* __restrict__ vals, int e) {
    int i = blockIdx.x * blockDim.x + threadIdx.x;
    if (i >= e) return;
    int r = rows[i];
    int pos = atomicAdd(&g_cur[r], 1);
    u64 p = ((u64)__float_as_uint(vals[i]) << 32) | (unsigned int)cols[i];
    g_ep[pos] = p;
}

// =====================================================================
// kernel 1: fused x@W1 / x@V / x^2@V^2
// One thread = one node, all 24 outputs. Weights in SMEM, broadcast LDS.
// SMEM operands consumed as ulonglong2 -> register pairs feed FFMA2 directly.
// =====================================================================
#define KCHUNK 32
#define XPITCH 36   // 32 + 4 pad, keeps 16B alignment

__global__ void __launch_bounds__(256, 2) k_gemmA(
    const float* __restrict__ x, const float* __restrict__ W1,
    const float* __restrict__ V, const float* __restrict__ gamma,
    const float* __restrict__ beta, int n)
{
    extern __shared__ float sm[];
    float* wT = sm;                 // [24][512]  (48 KB)
    float* xs = sm + 24 * NF;       // [256][36]  (36 KB)
    const int tid = threadIdx.x;
    const int nb  = blockIdx.x * 256;

    // stage combined weights, transposed to [out][k]
    for (int i = tid; i < NF * NH; i += 256) {
        int k = i >> 3, h = i & 7;
        float a = W1[i];
        float b = V[i];
        wT[h * NF + k]        = a;
        wT[(8 + h) * NF + k]  = b;
        wT[(16 + h) * NF + k] = b * b;
    }

    u64 a1[8], av[8], a2[8];
#pragma unroll
    for (int h = 0; h < 8; h++) { a1[h] = 0ull; av[h] = 0ull; a2[h] = 0ull; }

    for (int kc = 0; kc < NF; kc += KCHUNK) {
        __syncthreads();
        // stage x chunk [256 nodes][32 k] coalesced
        for (int idx = tid; idx < 256 * 8; idx += 256) {
            int r = idx >> 3, c4 = idx & 7;
            int gn = nb + r;
            float4 val = make_float4(0.f, 0.f, 0.f, 0.f);
            if (gn < n) val = *(const float4*)(x + (size_t)gn * NF + kc + c4 * 4);
            *(float4*)(xs + r * XPITCH + c4 * 4) = val;
        }
        __syncthreads();

#pragma unroll 4
        for (int kk = 0; kk < KCHUNK; kk += 4) {
            ulonglong2 xp = *(const ulonglong2*)(xs + tid * XPITCH + kk);
            u64 xA = xp.x, xB = xp.y, xA2, xB2;
            MUL2(xA2, xA, xA);
            MUL2(xB2, xB, xB);
            const float* wb = wT + kc + kk;
#pragma unroll
            for (int h = 0; h < 8; h++) {
                ulonglong2 w1p = *(const ulonglong2*)(wb + h * NF);          // broadcast
                ulonglong2 wvp = *(const ulonglong2*)(wb + (8 + h) * NF);    // broadcast
                ulonglong2 w2p = *(const ulonglong2*)(wb + (16 + h) * NF);   // broadcast
                FMA2(a1[h], xA,  w1p.x); FMA2(a1[h], xB,  w1p.y);
                FMA2(av[h], xA,  wvp.x); FMA2(av[h], xB,  wvp.y);
                FMA2(a2[h], xA2, w2p.x); FMA2(a2[h], xB2, w2p.y);
            }
        }
    }

    int node = nb + tid;
    if (node < n) {
#pragma unroll
        for (int h = 0; h < 8; h++) {
            float l0, l1;
            UNPACK2(l0, l1, a1[h]); float s1v  = l0 + l1;
            UNPACK2(l0, l1, av[h]); float xv   = l0 + l1;
            UNPACK2(l0, l1, a2[h]); float x2v2 = l0 + l1;
            float r = 0.5f * (xv * xv - x2v2);
            r = r > 0.f ? r : 0.f;
            g_s1[(size_t)node * NH + h] = s1v;
            g_xr[(size_t)node * NH + h] = gamma[h] * r + beta[h];
        }
    }
}

// =====================================================================
// kernel 2: pull-SpMM #1 fused with bias/relu/merge/h@W2
// 8 lanes per row (one per feature), 4 rows per warp, 32 rows per block.
// =====================================================================
__global__ void __launch_bounds__(256) k_spmm1mid(
    const float* __restrict__ b1, const float* __restrict__ W2, int n)
{
    __shared__ float w2s[NH * NC];
    __shared__ float b1s[NH];
    int t = threadIdx.x;
    if (t < NH * NC) w2s[t] = W2[t];
    if (t < NH)      b1s[t] = b1[t];
    __syncthreads();

    int j   = t & 7;
    int grp = t >> 3;                    // 0..31
    int r   = blockIdx.x * 32 + grp;
    bool valid = r < n;
    int rc = valid ? r : (n - 1);
    int start = g_offs[rc], end = g_offs[rc + 1];

    float acc = 0.f, accB = 0.f;
    int i = start;
    for (; i + 2 <= end; i += 2) {
        u64 p0 = g_ep[i], p1 = g_ep[i + 1];
        int   c0 = (int)(unsigned)p0,  c1 = (int)(unsigned)p1;
        float v0 = __uint_as_float((unsigned)(p0 >> 32));
        float v1 = __uint_as_float((unsigned)(p1 >> 32));
        acc  = fmaf(v0, g_s1[(size_t)c0 * NH + j], acc);
        accB = fmaf(v1, g_s1[(size_t)c1 * NH + j], accB);
    }
    if (i < end) {
        u64 p0 = g_ep[i];
        float v0 = __uint_as_float((unsigned)(p0 >> 32));
        acc = fmaf(v0, g_s1[(size_t)((int)(unsigned)p0) * NH + j], acc);
    }
    acc += accB;

    float l = acc + b1s[j];
    l = l > 0.f ? l : 0.f;
    float h = 0.5f * (l + (valid ? g_xr[(size_t)r * NH + j] : 0.f));

    // h @ W2 via width-8 shfl broadcast
    float o0 = 0.f, o1 = 0.f;
#pragma unroll
    for (int jj = 0; jj < 8; jj++) {
        float hv = __shfl_sync(0xffffffffu, h, jj, 8);
        o0 = fmaf(hv, w2s[jj * NC + j],     o0);
        o1 = fmaf(hv, w2s[jj * NC + j + 8], o1);
    }
    if (valid) {
        g_s2[(size_t)r * NC + j]     = o0;
        g_s2[(size_t)r * NC + j + 8] = o1;
    }
}

// =====================================================================
// kernel 3: pull-SpMM #2 fused with +b2 and log_softmax
// 16 lanes per row (one per class), 2 rows per warp, 16 rows per block.
// =====================================================================
__global__ void __launch_bounds__(256) k_spmm2lsm(
    const float* __restrict__ b2, float* __restrict__ out, int n)
{
    __shared__ float b2s[NC];
    int t = threadIdx.x;
    if (t < NC) b2s[t] = b2[t];
    __syncthreads();

    int c   = t & 15;
    int grp = t >> 4;                    // 0..15
    int r   = blockIdx.x * 16 + grp;
    bool valid = r < n;
    int rc = valid ? r : (n - 1);
    int start = g_offs[rc], end = g_offs[rc + 1];

    float acc = 0.f, accB = 0.f;
    int i = start;
    for (; i + 2 <= end; i += 2) {
        u64 p0 = g_ep[i], p1 = g_ep[i + 1];
        int   c0 = (int)(unsigned)p0,  c1 = (int)(unsigned)p1;
        float v0 = __uint_as_float((unsigned)(p0 >> 32));
        float v1 = __uint_as_float((unsigned)(p1 >> 32));
        acc  = fmaf(v0, g_s2[(size_t)c0 * NC + c], acc);
        accB = fmaf(v1, g_s2[(size_t)c1 * NC + c], accB);
    }
    if (i < end) {
        u64 p0 = g_ep[i];
        float v0 = __uint_as_float((unsigned)(p0 >> 32));
        acc = fmaf(v0, g_s2[(size_t)((int)(unsigned)p0) * NC + c], acc);
    }
    float v = acc + accB + b2s[c];

    float m = v;
#pragma unroll
    for (int d = 8; d; d >>= 1) m = fmaxf(m, __shfl_xor_sync(~0u, m, d, 16));
    float s = __expf(v - m);
#pragma unroll
    for (int d = 8; d; d >>= 1) s += __shfl_xor_sync(~0u, s, d, 16);
    if (valid) out[(size_t)r * NC + c] = v - m - __logf(s);
}

// ---------------- launcher -------------------------------------------
extern "C" void kernel_launch(void* const* d_in, const int* in_sizes, int n_in,
                              void* d_out, int out_size)
{
    const float* x     = (const float*)d_in[0];
    const int*   rows  = (const int*)d_in[1];
    const int*   cols  = (const int*)d_in[2];
    const float* vals  = (const float*)d_in[3];
    const float* W1    = (const float*)d_in[4];
    const float* b1    = (const float*)d_in[5];
    const float* W2    = (const float*)d_in[6];
    const float* b2    = (const float*)d_in[7];
    const float* V     = (const float*)d_in[8];
    const float* gamma = (const float*)d_in[9];
    const float* beta  = (const float*)d_in[10];
    float* out = (float*)d_out;

    int n = in_sizes[0] / NF;   // 100000
    int e = in_sizes[1];        // 3200000

    int smem = (24 * NF + 256 * XPITCH) * (int)sizeof(float);
    cudaFuncSetAttribute(k_gemmA, cudaFuncAttributeMaxDynamicSharedMemorySize, smem);

    int nblkScan = (n + SCAN_ELEMS - 1) / SCAN_ELEMS;   // 98 for n=100000

    // ---- CSR build ----
    k_zero_cnt<<<(n + 255) / 256, 256>>>(n);
    k_hist<<<(e + 255) / 256, 256>>>(rows, e);
    k_scanA<<<nblkScan, 256>>>(n);
    k_scanB<<<1, 128>>>(nblkScan);
    k_scanC<<<nblkScan, 256>>>(n, e);

    // ---- fused input GEMM (independent of CSR; overlaps nothing, fine) ----
    k_gemmA<<<(n + 255) / 256, 256, smem>>>(x, W1, V, gamma, beta, n);

    // ---- scatter edges into CSR order ----
    k_scatter<<<(e + 255) / 256, 256>>>(rows, cols, vals, e);

    // ---- pull SpMM 1 + mid fusion ----
    k_spmm1mid<<<(n + 31) / 32, 256>>>(b1, W2, n);

    // ---- pull SpMM 2 + bias + log_softmax ----
    k_spmm2lsm<<<(n + 15) / 16, 256>>>(b2, out, n);
}

// round 4
// speedup vs baseline: 1.4856x; 1.0672x over previous
#include <cuda_runtime.h>

#define NMAX  100000
#define EMAX  3200000
#define NF    512
#define NH    8
#define NC    16

// ---------------- scratch (no allocations allowed) ----------------
__device__ float g_s1[NMAX * NH];          // x @ W1 (pre-spmm)
__device__ float g_xr[NMAX * NH];          // affine(relu(bi-interaction))
__device__ float g_s2[NMAX * NC];          // h @ W2
__device__ int   g_cnt[NMAX];              // per-row degree
__device__ int   g_offs[NMAX];             // CSR row range start (arbitrary order)
__device__ int   g_cur[NMAX];              // scatter cursors
__device__ int   g_total;                  // global range allocator
__device__ unsigned long long g_ep[EMAX];  // packed edges: lo=col, hi=val bits

typedef unsigned long long u64;

// ---------------- f32x2 helpers (FFMA2 = full-rate fp32 on sm_103a) ---
#define UNPACK2(lo, hi, in) \
    asm("mov.b64 {%0, %1}, %2;" : "=f"(lo), "=f"(hi) : "l"(in))
#define MUL2(out, a, b) \
    asm("mul.rn.f32x2 %0, %1, %2;" : "=l"(out) : "l"(a), "l"(b))
#define FMA2(acc, a, b) \
    asm("fma.rn.f32x2 %0, %1, %2, %0;" : "+l"(acc) : "l"(a), "l"(b))

// =====================================================================
// launch 0: zero counters
// =====================================================================
__global__ void k_zero(int n) {
    int i = blockIdx.x * blockDim.x + threadIdx.x;
    int i4 = i * 4;
    if (i4 + 3 < n) {
        *(int4*)(g_cnt + i4) = make_int4(0, 0, 0, 0);
    } else {
        for (int q = 0; q < 4; q++) if (i4 + q < n) g_cnt[i4 + q] = 0;
    }
    if (i == 0) g_total = 0;
}

// =====================================================================
// launch 1: degree histogram
// =====================================================================
__global__ void k_hist(const int* __restrict__ rows, int e) {
    int i = blockIdx.x * blockDim.x + threadIdx.x;
    if (i < e) atomicAdd(&g_cnt[rows[i]], 1);
}

// =====================================================================
// launch 2: allocate contiguous per-row ranges (block scan + 1 atomic/block)
// Range order across blocks is arbitrary — SpMM only needs contiguity.
// =====================================================================
__global__ void __launch_bounds__(256) k_alloc(int n) {
    __shared__ int wsum[8];
    __shared__ int wpref[8];
    __shared__ int blockBase;
    int t = threadIdx.x;
    int lane = t & 31, wid = t >> 5;
    int base = blockIdx.x * 1024 + t * 4;

    int v[4]; int s = 0;
#pragma unroll
    for (int q = 0; q < 4; q++) { int i = base + q; v[q] = (i < n) ? g_cnt[i] : 0; s += v[q]; }

    int sc = s;  // inclusive warp scan
#pragma unroll
    for (int d = 1; d < 32; d <<= 1) {
        int u = __shfl_up_sync(~0u, sc, d);
        if (lane >= d) sc += u;
    }
    if (lane == 31) wsum[wid] = sc;
    __syncthreads();
    if (t == 0) {
        int run = 0;
#pragma unroll
        for (int w = 0; w < 8; w++) { wpref[w] = run; run += wsum[w]; }
        blockBase = atomicAdd(&g_total, run);
    }
    __syncthreads();

    int run = blockBase + wpref[wid] + (sc - s);
#pragma unroll
    for (int q = 0; q < 4; q++) {
        int i = base + q;
        if (i < n) {
            g_offs[i] = run;
            g_cur[i]  = run;
            run += v[q];
        }
    }
}

// =====================================================================
// launch 3 (PROFILED SLOT): scatter edges into CSR order
// =====================================================================
__global__ void k_scatter(const int* __restrict__ rows, const int* __restrict__ cols,
                          const float* __restrict__ vals, int e) {
    int i = blockIdx.x * blockDim.x + threadIdx.x;
    if (i >= e) return;
    int r = rows[i];
    int pos = atomicAdd(&g_cur[r], 1);
    u64 p = ((u64)__float_as_uint(vals[i]) << 32) | (unsigned int)cols[i];
    g_ep[pos] = p;
}

// =====================================================================
// launch 4: fused x@W1 / x@V / x^2@V^2 — persistent blocks
// 128 threads, 3 blocks/SM, weights staged once per block.
// =====================================================================
#define KCHUNK 32
#define XPITCH 36   // 32 + 4 pad: 16B aligned, conflict-free LDS.128

__global__ void __launch_bounds__(128, 3) k_gemmA(
    const float* __restrict__ x, const float* __restrict__ W1,
    const float* __restrict__ V, const float* __restrict__ gamma,
    const float* __restrict__ beta, int n)
{
    extern __shared__ float sm[];
    float* wT = sm;                 // [24][512]  (48 KB)
    float* xs = sm + 24 * NF;       // [128][36]  (18 KB)
    const int tid = threadIdx.x;

    // stage combined weights once per block, transposed to [out][k]
    for (int i = tid; i < NF * NH; i += 128) {
        int k = i >> 3, h = i & 7;
        float a = W1[i];
        float b = V[i];
        wT[h * NF + k]        = a;
        wT[(8 + h) * NF + k]  = b;
        wT[(16 + h) * NF + k] = b * b;
    }

    const int ntiles = (n + 127) >> 7;
    for (int tile = blockIdx.x; tile < ntiles; tile += gridDim.x) {
        const int nb = tile << 7;

        u64 a1[8], av[8], a2[8];
#pragma unroll
        for (int h = 0; h < 8; h++) { a1[h] = 0ull; av[h] = 0ull; a2[h] = 0ull; }

        for (int kc = 0; kc < NF; kc += KCHUNK) {
            __syncthreads();
            // stage x chunk [128 nodes][32 k] coalesced: 1024 float4 / 128 thr
            for (int idx = tid; idx < 128 * 8; idx += 128) {
                int r = idx >> 3, c4 = idx & 7;
                int gn = nb + r;
                float4 val = make_float4(0.f, 0.f, 0.f, 0.f);
                if (gn < n) val = *(const float4*)(x + (size_t)gn * NF + kc + c4 * 4);
                *(float4*)(xs + r * XPITCH + c4 * 4) = val;
            }
            __syncthreads();

#pragma unroll 4
            for (int kk = 0; kk < KCHUNK; kk += 4) {
                ulonglong2 xp = *(const ulonglong2*)(xs + tid * XPITCH + kk);
                u64 xA = xp.x, xB = xp.y, xA2, xB2;
                MUL2(xA2, xA, xA);
                MUL2(xB2, xB, xB);
                const float* wb = wT + kc + kk;
#pragma unroll
                for (int h = 0; h < 8; h++) {
                    ulonglong2 w1p = *(const ulonglong2*)(wb + h * NF);          // broadcast
                    ulonglong2 wvp = *(const ulonglong2*)(wb + (8 + h) * NF);    // broadcast
                    ulonglong2 w2p = *(const ulonglong2*)(wb + (16 + h) * NF);   // broadcast
                    FMA2(a1[h], xA,  w1p.x); FMA2(a1[h], xB,  w1p.y);
                    FMA2(av[h], xA,  wvp.x); FMA2(av[h], xB,  wvp.y);
                    FMA2(a2[h], xA2, w2p.x); FMA2(a2[h], xB2, w2p.y);
                }
            }
        }

        int node = nb + tid;
        if (node < n) {
#pragma unroll
            for (int h = 0; h < 8; h++) {
                float l0, l1;
                UNPACK2(l0, l1, a1[h]); float s1v  = l0 + l1;
                UNPACK2(l0, l1, av[h]); float xv   = l0 + l1;
                UNPACK2(l0, l1, a2[h]); float x2v2 = l0 + l1;
                float r = 0.5f * (xv * xv - x2v2);
                r = r > 0.f ? r : 0.f;
                g_s1[(size_t)node * NH + h] = s1v;
                g_xr[(size_t)node * NH + h] = gamma[h] * r + beta[h];
            }
        }
        __syncthreads();
    }
}

// =====================================================================
// launch 5: pull-SpMM #1 fused with bias/relu/merge/h@W2
// 8 lanes per row, 4 rows per warp.
// =====================================================================
__global__ void __launch_bounds__(256) k_spmm1mid(
    const float* __restrict__ b1, const float* __restrict__ W2, int n)
{
    __shared__ float w2s[NH * NC];
    __shared__ float b1s[NH];
    int t = threadIdx.x;
    if (t < NH * NC) w2s[t] = W2[t];
    if (t < NH)      b1s[t] = b1[t];
    __syncthreads();

    int j   = t & 7;
    int grp = t >> 3;
    int r   = blockIdx.x * 32 + grp;
    bool valid = r < n;
    int rc = valid ? r : (n - 1);
    int start = g_offs[rc];
    int end   = start + g_cnt[rc];

    float acc = 0.f, accB = 0.f;
    int i = start;
    for (; i + 2 <= end; i += 2) {
        u64 p0 = g_ep[i], p1 = g_ep[i + 1];
        int   c0 = (int)(unsigned)p0,  c1 = (int)(unsigned)p1;
        float v0 = __uint_as_float((unsigned)(p0 >> 32));
        float v1 = __uint_as_float((unsigned)(p1 >> 32));
        acc  = fmaf(v0, __ldg(&g_s1[(size_t)c0 * NH + j]), acc);
        accB = fmaf(v1, __ldg(&g_s1[(size_t)c1 * NH + j]), accB);
    }
    if (i < end) {
        u64 p0 = g_ep[i];
        float v0 = __uint_as_float((unsigned)(p0 >> 32));
        acc = fmaf(v0, __ldg(&g_s1[(size_t)((int)(unsigned)p0) * NH + j]), acc);
    }
    acc += accB;

    float l = acc + b1s[j];
    l = l > 0.f ? l : 0.f;
    float h = 0.5f * (l + (valid ? g_xr[(size_t)r * NH + j] : 0.f));

    float o0 = 0.f, o1 = 0.f;
#pragma unroll
    for (int jj = 0; jj < 8; jj++) {
        float hv = __shfl_sync(0xffffffffu, h, jj, 8);
        o0 = fmaf(hv, w2s[jj * NC + j],     o0);
        o1 = fmaf(hv, w2s[jj * NC + j + 8], o1);
    }
    if (valid) {
        g_s2[(size_t)r * NC + j]     = o0;
        g_s2[(size_t)r * NC + j + 8] = o1;
    }
}

// =====================================================================
// launch 6: pull-SpMM #2 fused with +b2 and log_softmax
// 16 lanes per row, 2 rows per warp.
// =====================================================================
__global__ void __launch_bounds__(256) k_spmm2lsm(
    const float* __restrict__ b2, float* __restrict__ out, int n)
{
    __shared__ float b2s[NC];
    int t = threadIdx.x;
    if (t < NC) b2s[t] = b2[t];
    __syncthreads();

    int c   = t & 15;
    int grp = t >> 4;
    int r   = blockIdx.x * 16 + grp;
    bool valid = r < n;
    int rc = valid ? r : (n - 1);
    int start = g_offs[rc];
    int end   = start + g_cnt[rc];

    float acc = 0.f, accB = 0.f;
    int i = start;
    for (; i + 2 <= end; i += 2) {
        u64 p0 = g_ep[i], p1 = g_ep[i + 1];
        int   c0 = (int)(unsigned)p0,  c1 = (int)(unsigned)p1;
        float v0 = __uint_as_float((unsigned)(p0 >> 32));
        float v1 = __uint_as_float((unsigned)(p1 >> 32));
        acc  = fmaf(v0, __ldg(&g_s2[(size_t)c0 * NC + c]), acc);
        accB = fmaf(v1, __ldg(&g_s2[(size_t)c1 * NC + c]), accB);
    }
    if (i < end) {
        u64 p0 = g_ep[i];
        float v0 = __uint_as_float((unsigned)(p0 >> 32));
        acc = fmaf(v0, __ldg(&g_s2[(size_t)((int)(unsigned)p0) * NC + c]), acc);
    }
    float v = acc + accB + b2s[c];

    float m = v;
#pragma unroll
    for (int d = 8; d; d >>= 1) m = fmaxf(m, __shfl_xor_sync(~0u, m, d, 16));
    float s = __expf(v - m);
#pragma unroll
    for (int d = 8; d; d >>= 1) s += __shfl_xor_sync(~0u, s, d, 16);
    if (valid) out[(size_t)r * NC + c] = v - m - __logf(s);
}

// ---------------- launcher -------------------------------------------
extern "C" void kernel_launch(void* const* d_in, const int* in_sizes, int n_in,
                              void* d_out, int out_size)
{
    const float* x     = (const float*)d_in[0];
    const int*   rows  = (const int*)d_in[1];
    const int*   cols  = (const int*)d_in[2];
    const float* vals  = (const float*)d_in[3];
    const float* W1    = (const float*)d_in[4];
    const float* b1    = (const float*)d_in[5];
    const float* W2    = (const float*)d_in[6];
    const float* b2    = (const float*)d_in[7];
    const float* V     = (const float*)d_in[8];
    const float* gamma = (const float*)d_in[9];
    const float* beta  = (const float*)d_in[10];
    float* out = (float*)d_out;

    int n = in_sizes[0] / NF;   // 100000
    int e = in_sizes[1];        // 3200000

    int smem = (24 * NF + 128 * XPITCH) * (int)sizeof(float);
    cudaFuncSetAttribute(k_gemmA, cudaFuncAttributeMaxDynamicSharedMemorySize, smem);

    // launch 0-2: CSR skeleton
    k_zero<<<(n + 1023) / 1024, 256>>>(n);
    k_hist<<<(e + 255) / 256, 256>>>(rows, e);
    k_alloc<<<(n + 1023) / 1024, 256>>>(n);

    // launch 3 (profiled slot): scatter — the atomic-return suspect
    k_scatter<<<(e + 255) / 256, 256>>>(rows, cols, vals, e);

    // launch 4: fused input GEMM (persistent)
    k_gemmA<<<444, 128, smem>>>(x, W1, V, gamma, beta, n);

    // launch 5: pull SpMM 1 + mid fusion
    k_spmm1mid<<<(n + 31) / 32, 256>>>(b1, W2, n);

    // launch 6: pull SpMM 2 + bias + log_softmax
    k_spmm2lsm<<<(n + 15) / 16, 256>>>(b2, out, n);
}